// round 12
// baseline (speedup 1.0000x reference)
#include <cuda_runtime.h>
#include <cuda_bf16.h>
#include <cstdint>

// CIN (xDeepFM) fused 3-layer kernel via mma.sync (HMMA) bf16 3-term split.
// Round 11: R7 base, but each CTA's 8 warps are split into two independent
// barrier domains (warps 0-3 = wn0, warps 4-7 = wn1) using named barriers.
// Each domain owns its n-half of every W stage (cp.async + ldsm + bar.sync),
// so per SMSP there are 4 independent instruction streams (2 CTAs x 2 groups)
// and the per-chunk no-MMA tail of one domain is covered by the others.

#define NT 256
#define KCH 576                 // total 16-wide k chunks: 64 + 256 + 256
#define WTERM 4096              // 128 n-rows * 32B (16 bf16), swizzled
#define CHUNK_BYTES (2 * WTERM) // 8192: hi term + lo term
#define NSTAGE 3
#define HALF 2048               // bytes per n-half of one term

// smem byte offsets
#define SM_X0T   0                  // 128 rows * 36 f32 = 18432
#define SM_ST    18432              // 128 rows * 132 f32 = 67584
#define SM_W     86016              // 3 stages * 8192 = 24576
#define SM_BIAS  110592             // 384 f32 = 1536
#define SMEM_TOTAL 112128

__device__ __align__(16) unsigned char WT_buf[(size_t)KCH * CHUNK_BYTES]; // 4.7MB

// ------------- helpers -------------
__device__ __forceinline__ uint32_t smem_u32(const void* p) {
    uint32_t a;
    asm("{ .reg .u64 t; cvta.to.shared.u64 t, %1; cvt.u32.u64 %0, t; }" : "=r"(a) : "l"(p));
    return a;
}
__device__ __forceinline__ uint32_t pkbf(float lo, float hi) {
    uint32_t r;  // first asm operand -> high half
    asm("cvt.rn.bf16x2.f32 %0, %1, %2;" : "=r"(r) : "f"(hi), "f"(lo));
    return r;
}
__device__ __forceinline__ float bflo(uint32_t p) { return __uint_as_float(p << 16); }
__device__ __forceinline__ float bfhi(uint32_t p) { return __uint_as_float(p & 0xffff0000u); }

__device__ __forceinline__ void ldsm4(uint32_t a, uint32_t& r0, uint32_t& r1,
                                      uint32_t& r2, uint32_t& r3) {
    asm volatile("ldmatrix.sync.aligned.m8n8.x4.shared.b16 {%0,%1,%2,%3}, [%4];"
                 : "=r"(r0), "=r"(r1), "=r"(r2), "=r"(r3) : "r"(a));
}
__device__ __forceinline__ void mma16816(float* c, const uint32_t* a, uint32_t b0, uint32_t b1) {
    asm volatile("mma.sync.aligned.m16n8k16.row.col.f32.bf16.bf16.f32 "
                 "{%0,%1,%2,%3}, {%4,%5,%6,%7}, {%8,%9}, {%0,%1,%2,%3};"
                 : "+f"(c[0]), "+f"(c[1]), "+f"(c[2]), "+f"(c[3])
                 : "r"(a[0]), "r"(a[1]), "r"(a[2]), "r"(a[3]), "r"(b0), "r"(b1));
}
__device__ __forceinline__ void cpasync16(uint32_t dst, const void* src) {
    asm volatile("cp.async.cg.shared.global [%0], [%1], 16;" :: "r"(dst), "l"(src) : "memory");
}
#define CP_COMMIT() asm volatile("cp.async.commit_group;" ::: "memory")
#define CP_WAIT1()  asm volatile("cp.async.wait_group 1;" ::: "memory")
__device__ __forceinline__ void group_bar(int id) {
    asm volatile("bar.sync %0, 128;" :: "r"(id) : "memory");
}

// swizzled byte offset of the 16B half (n-row, khalf) within one term
__device__ __host__ __forceinline__ int wsw(int n, int khalf) {
    return n * 32 + ((khalf ^ ((n >> 2) & 1)) << 4);
}

// ------------- prep: split W -> bf16 hi/lo, swizzled chunk layout == smem -------------
__global__ void prep_w(const float* __restrict__ W0, const float* __restrict__ W1,
                       const float* __restrict__ W2) {
    int i = blockIdx.x * blockDim.x + threadIdx.x;   // over 9216*128
    if (i >= 9216 * 128) return;
    int k = i >> 7, n = i & 127;
    float w;
    if (k < 1024)      w = W0[k * 128 + n];
    else if (k < 5120) w = W1[(k - 1024) * 128 + n];
    else               w = W2[(k - 5120) * 128 + n];
    __nv_bfloat16 hb = __float2bfloat16(w);
    __nv_bfloat16 lb = __float2bfloat16(w - __bfloat162float(hb));
    int c = k >> 4, kk = k & 15;
    int off = wsw(n, kk >> 3) + (kk & 7) * 2;
    unsigned char* base = WT_buf + (size_t)c * CHUNK_BYTES + off;
    *(__nv_bfloat16*)(base)         = hb;   // hi term
    *(__nv_bfloat16*)(base + WTERM) = lb;   // lo term
}

// ------------- main kernel -------------
__global__ void __launch_bounds__(NT, 2)
cin_hmma_kernel(const float* __restrict__ X,
                const float* __restrict__ B0, const float* __restrict__ B1,
                const float* __restrict__ B2, float* __restrict__ out)
{
    extern __shared__ __align__(16) char smem[];
    float* x0t  = (float*)(smem + SM_X0T);   // [row][36] (f stride)
    float* st   = (float*)(smem + SM_ST);    // [row][132] (g stride)
    float* bias = (float*)(smem + SM_BIAS);  // [384]
    const uint32_t wsm = smem_u32(smem) + SM_W;

    const int tid = threadIdx.x, wid = tid >> 5, lane = tid & 31;
    // Warp grid: wm = wid&3 (batch), wn = wid>>2 (n-half) -> barrier group.
    // SMSP s hosts wid s (wn0) and wid s+4 (wn1): one warp per domain.
    const int wm = wid & 3, wn = wid >> 2;
    const int barid = 1 + wn;                  // named barrier per group
    const int gtid = tid & 127;                // thread index within group
    const int b0g = blockIdx.x * 4;
    const int r0 = lane >> 2;                  // row-in-frag 0..7
    const int c0 = (lane & 3) * 2;             // col pair base

    // group's cp.async slice offsets within a stage (this group's n-half)
    const uint32_t cp_off0 = (uint32_t)(wn * HALF + gtid * 16);           // term 0
    const uint32_t cp_off1 = (uint32_t)(WTERM + wn * HALF + gtid * 16);   // term 1

    // ---- prologue: each group cps its halves of chunks 0,1 (1 commit/chunk) ----
    {
        const unsigned char* g0 = WT_buf;
        cpasync16(wsm + cp_off0, g0 + cp_off0);
        cpasync16(wsm + cp_off1, g0 + cp_off1);
        CP_COMMIT();
        const unsigned char* g1 = WT_buf + CHUNK_BYTES;
        cpasync16(wsm + CHUNK_BYTES + cp_off0, g1 + cp_off0);
        cpasync16(wsm + CHUNK_BYTES + cp_off1, g1 + cp_off1);
        CP_COMMIT();
    }

    // ---- load x0 transposed + init state + bias ----
    {
        const float* Xb = X + (size_t)b0g * 1024;
        for (int i = tid; i < 4096; i += NT) {
            int b = i >> 10, f = (i >> 5) & 31, d = i & 31;
            float v = Xb[i];
            int row = b * 32 + d;
            x0t[row * 36 + f] = v;
            st[row * 132 + f] = v;     // layer-0 state = x0 (g = f)
        }
        for (int i = tid; i < 128; i += NT) {
            bias[i] = B0[i]; bias[128 + i] = B1[i]; bias[256 + i] = B2[i];
        }
    }
    CP_WAIT1();          // chunk 0 landed (chunk 1 may still be in flight)
    __syncthreads();     // x0t/st/bias + everyone's chunk-0 half visible

    // per-j ldsm swizzled offsets within a term (this warp's n-half)
    const int kh = (lane >> 3) & 1;
    uint32_t nroff[4];
    #pragma unroll
    for (int j = 0; j < 4; ++j) {
        const int nrow = (wn * 8 + 2 * j + ((lane >> 4) & 1)) * 8 + (lane & 7);
        nroff[j] = (uint32_t)wsw(nrow, kh);
    }

    uint32_t bh[4][4], bl[4][4];    // current chunk's B fragments
    uint32_t ah[2][4], al[2][4];    // current chunk's A fragments

    // prime B for chunk 0 (stage 0)
    #pragma unroll
    for (int j = 0; j < 4; ++j)
        ldsm4(wsm + nroff[j], bh[j][0], bh[j][1], bh[j][2], bh[j][3]);
    #pragma unroll
    for (int j = 0; j < 4; ++j)
        ldsm4(wsm + WTERM + nroff[j], bl[j][0], bl[j][1], bl[j][2], bl[j][3]);

    int cg = 0;      // global chunk counter
    int scur = 0;    // stage of current chunk
    int swr = 2;     // stage cp.async writes (cg+2)

    #pragma unroll 1
    for (int l = 0; l < 3; ++l) {
        const int lg2 = (l == 0) ? 1 : 3;        // chunks per f = fk/16
        const int nchunk = (l == 0) ? 64 : 256;

        float acc[2][8][4];
        #pragma unroll
        for (int fr = 0; fr < 2; ++fr)
            #pragma unroll
            for (int nt = 0; nt < 8; ++nt)
                #pragma unroll
                for (int q = 0; q < 4; ++q) acc[fr][nt][q] = 0.f;

        auto build_A = [&](int cc) {
            const int f = cc >> lg2;
            const int g0 = ((cc & ((1 << lg2) - 1)) << 4) + c0;
            #pragma unroll
            for (int fr = 0; fr < 2; ++fr) {
                #pragma unroll
                for (int j2 = 0; j2 < 2; ++j2) {
                    const int row = wm * 32 + r0 + fr * 16 + j2 * 8;
                    const float x = x0t[row * 36 + f];
                    const float2 p0 = *(const float2*)(st + row * 132 + g0);
                    const float2 p1 = *(const float2*)(st + row * 132 + g0 + 8);
                    float z00 = x * p0.x, z01 = x * p0.y;
                    float z10 = x * p1.x, z11 = x * p1.y;
                    uint32_t h0 = pkbf(z00, z01), h1 = pkbf(z10, z11);
                    al[fr][j2]     = pkbf(z00 - bflo(h0), z01 - bfhi(h0));
                    al[fr][2 + j2] = pkbf(z10 - bflo(h1), z11 - bfhi(h1));
                    ah[fr][j2]     = h0;
                    ah[fr][2 + j2] = h1;
                }
            }
        };

        build_A(0);   // state is synced at this point

        #pragma unroll 1
        for (int cc = 0; cc < nchunk; ++cc) {
            // ---- issue cp.async for chunk cg+2 (this group's half of stage
            //      swr; own-group readers of that half finished pre-previous
            //      group barrier) ----
            if (cg + 2 < KCH) {
                const unsigned char* src = WT_buf + (size_t)(cg + 2) * CHUNK_BYTES;
                const uint32_t dst = wsm + (uint32_t)swr * CHUNK_BYTES;
                cpasync16(dst + cp_off0, src + cp_off0);
                cpasync16(dst + cp_off1, src + cp_off1);
                CP_COMMIT();
            }

            // ---- 48-MMA burst for chunk cg (A and B already in registers) ----
            #pragma unroll
            for (int j = 0; j < 4; ++j) {
                mma16816(acc[0][2 * j],     ah[0], bh[j][0], bh[j][1]);
                mma16816(acc[1][2 * j],     ah[1], bh[j][0], bh[j][1]);
                mma16816(acc[0][2 * j + 1], ah[0], bh[j][2], bh[j][3]);
                mma16816(acc[1][2 * j + 1], ah[1], bh[j][2], bh[j][3]);
                mma16816(acc[0][2 * j],     al[0], bh[j][0], bh[j][1]);
                mma16816(acc[1][2 * j],     al[1], bh[j][0], bh[j][1]);
                mma16816(acc[0][2 * j + 1], al[0], bh[j][2], bh[j][3]);
                mma16816(acc[1][2 * j + 1], al[1], bh[j][2], bh[j][3]);
                mma16816(acc[0][2 * j],     ah[0], bl[j][0], bl[j][1]);
                mma16816(acc[1][2 * j],     ah[1], bl[j][0], bl[j][1]);
                mma16816(acc[0][2 * j + 1], ah[0], bl[j][2], bl[j][3]);
                mma16816(acc[1][2 * j + 1], ah[1], bl[j][2], bl[j][3]);
            }

            // ---- A for next chunk of this layer ----
            if (cc + 1 < nchunk) build_A(cc + 1);

            // ---- B for chunk cg+1 (its cp group has ~2 chunks of slack;
            //      wait_group 1 leaves cg+2's group pending) ----
            if (cg + 1 < KCH) {
                CP_WAIT1();
                const uint32_t snx = wsm + (uint32_t)((scur + 1) % NSTAGE) * CHUNK_BYTES;
                #pragma unroll
                for (int j = 0; j < 4; ++j)
                    ldsm4(snx + nroff[j], bh[j][0], bh[j][1], bh[j][2], bh[j][3]);
                #pragma unroll
                for (int j = 0; j < 4; ++j)
                    ldsm4(snx + WTERM + nroff[j], bl[j][0], bl[j][1], bl[j][2], bl[j][3]);
            }

            // ---- group-local WAR fence (this group's half of the ring) ----
            group_bar(barid);

            scur = (scur + 1) % NSTAGE;
            swr  = (swr + 1) % NSTAGE;
            ++cg;
        }

        // ---- cross-group fence: both groups' build_A reads of st done
        //      before anyone overwrites st (groups share st rows) ----
        __syncthreads();

        // ---- epilogue: output reduction (sum over d) + state update ----
        const int bgl = b0g + wm;
        #pragma unroll
        for (int nt = 0; nt < 8; ++nt) {
            float s0 = acc[0][nt][0] + acc[0][nt][2] + acc[1][nt][0] + acc[1][nt][2];
            float s1 = acc[0][nt][1] + acc[0][nt][3] + acc[1][nt][1] + acc[1][nt][3];
            #pragma unroll
            for (int off = 4; off <= 16; off <<= 1) {
                s0 += __shfl_xor_sync(0xffffffffu, s0, off);
                s1 += __shfl_xor_sync(0xffffffffu, s1, off);
            }
            if (lane < 4) {
                const int col = wn * 64 + nt * 8 + c0;
                float2 o;
                o.x = s0 + 32.0f * bias[l * 128 + col];
                o.y = s1 + 32.0f * bias[l * 128 + col + 1];
                *(float2*)(out + (size_t)bgl * 384 + l * 128 + col) = o;
            }
        }

        if (l < 2) {
            // state[row][h] = C[row][h] + bias_l[h]
            #pragma unroll
            for (int fr = 0; fr < 2; ++fr) {
                #pragma unroll
                for (int nt = 0; nt < 8; ++nt) {
                    const int col = wn * 64 + nt * 8 + c0;
                    const float bx = bias[l * 128 + col];
                    const float by = bias[l * 128 + col + 1];
                    const int rowa = wm * 32 + r0 + fr * 16;
                    float2 v0, v1;
                    v0.x = acc[fr][nt][0] + bx; v0.y = acc[fr][nt][1] + by;
                    v1.x = acc[fr][nt][2] + bx; v1.y = acc[fr][nt][3] + by;
                    *(float2*)(st + rowa * 132 + col)       = v0;
                    *(float2*)(st + (rowa + 8) * 132 + col) = v1;
                }
            }
            __syncthreads();   // state visible before next layer's A builds
        }
    }
}

extern "C" void kernel_launch(void* const* d_in, const int* in_sizes, int n_in,
                              void* d_out, int out_size) {
    const float* X  = (const float*)d_in[0];
    const float* W0 = (const float*)d_in[1];
    const float* W1 = (const float*)d_in[2];
    const float* W2 = (const float*)d_in[3];
    const float* B0 = (const float*)d_in[4];
    const float* B1 = (const float*)d_in[5];
    const float* B2 = (const float*)d_in[6];
    float* out = (float*)d_out;

    const int B = in_sizes[0] / 1024;

    cudaFuncSetAttribute(cin_hmma_kernel,
                         cudaFuncAttributeMaxDynamicSharedMemorySize, SMEM_TOTAL);

    prep_w<<<(9216 * 128 + 255) / 256, 256>>>(W0, W1, W2);
    cin_hmma_kernel<<<B / 4, NT, SMEM_TOTAL>>>(X, B0, B1, B2, out);
}

// round 13
// speedup vs baseline: 1.0334x; 1.0334x over previous
#include <cuda_runtime.h>
#include <cuda_bf16.h>
#include <cstdint>

// CIN (xDeepFM) fused 3-layer kernel via mma.sync (HMMA) bf16 3-term split.
// Round 12: exact R7 per-chunk event order (cp.async issue -> 48-MMA burst ->
// build_A(next) -> wait -> pre-barrier ldsm of next chunk), but __syncthreads
// only after every SECOND chunk. Safe because a cp.async at iter i targets
// stage (i+2)%3 whose last readers ran at iter i-2 (reuse distance 2), so a
// barrier at the end of each (even,odd) pair separates every WAR pair.

#define NT 256
#define KCH 576                 // total 16-wide k chunks: 64 + 256 + 256
#define WTERM 4096              // 128 n-rows * 32B (16 bf16), swizzled
#define CHUNK_BYTES (2 * WTERM) // 8192: hi term + lo term
#define NSTAGE 3

// smem byte offsets
#define SM_X0T   0                  // 128 rows * 36 f32 = 18432
#define SM_ST    18432              // 128 rows * 132 f32 = 67584
#define SM_W     86016              // 3 stages * 8192 = 24576
#define SM_BIAS  110592             // 384 f32 = 1536
#define SMEM_TOTAL 112128

__device__ __align__(16) unsigned char WT_buf[(size_t)KCH * CHUNK_BYTES]; // 4.7MB

// ------------- helpers -------------
__device__ __forceinline__ uint32_t smem_u32(const void* p) {
    uint32_t a;
    asm("{ .reg .u64 t; cvta.to.shared.u64 t, %1; cvt.u32.u64 %0, t; }" : "=r"(a) : "l"(p));
    return a;
}
__device__ __forceinline__ uint32_t pkbf(float lo, float hi) {
    uint32_t r;  // first asm operand -> high half
    asm("cvt.rn.bf16x2.f32 %0, %1, %2;" : "=r"(r) : "f"(hi), "f"(lo));
    return r;
}
__device__ __forceinline__ float bflo(uint32_t p) { return __uint_as_float(p << 16); }
__device__ __forceinline__ float bfhi(uint32_t p) { return __uint_as_float(p & 0xffff0000u); }

__device__ __forceinline__ void ldsm4(uint32_t a, uint32_t& r0, uint32_t& r1,
                                      uint32_t& r2, uint32_t& r3) {
    asm volatile("ldmatrix.sync.aligned.m8n8.x4.shared.b16 {%0,%1,%2,%3}, [%4];"
                 : "=r"(r0), "=r"(r1), "=r"(r2), "=r"(r3) : "r"(a));
}
__device__ __forceinline__ void mma16816(float* c, const uint32_t* a, uint32_t b0, uint32_t b1) {
    asm volatile("mma.sync.aligned.m16n8k16.row.col.f32.bf16.bf16.f32 "
                 "{%0,%1,%2,%3}, {%4,%5,%6,%7}, {%8,%9}, {%0,%1,%2,%3};"
                 : "+f"(c[0]), "+f"(c[1]), "+f"(c[2]), "+f"(c[3])
                 : "r"(a[0]), "r"(a[1]), "r"(a[2]), "r"(a[3]), "r"(b0), "r"(b1));
}
__device__ __forceinline__ void cpasync16(uint32_t dst, const void* src) {
    asm volatile("cp.async.cg.shared.global [%0], [%1], 16;" :: "r"(dst), "l"(src) : "memory");
}
#define CP_COMMIT() asm volatile("cp.async.commit_group;" ::: "memory")
#define CP_WAIT0()  asm volatile("cp.async.wait_group 0;" ::: "memory")
#define CP_WAIT1()  asm volatile("cp.async.wait_group 1;" ::: "memory")

// swizzled byte offset of the 16B half (n-row, khalf) within one term
__device__ __host__ __forceinline__ int wsw(int n, int khalf) {
    return n * 32 + ((khalf ^ ((n >> 2) & 1)) << 4);
}

// ------------- prep: split W -> bf16 hi/lo, swizzled chunk layout == smem -------------
__global__ void prep_w(const float* __restrict__ W0, const float* __restrict__ W1,
                       const float* __restrict__ W2) {
    int i = blockIdx.x * blockDim.x + threadIdx.x;   // over 9216*128
    if (i >= 9216 * 128) return;
    int k = i >> 7, n = i & 127;
    float w;
    if (k < 1024)      w = W0[k * 128 + n];
    else if (k < 5120) w = W1[(k - 1024) * 128 + n];
    else               w = W2[(k - 5120) * 128 + n];
    __nv_bfloat16 hb = __float2bfloat16(w);
    __nv_bfloat16 lb = __float2bfloat16(w - __bfloat162float(hb));
    int c = k >> 4, kk = k & 15;
    int off = wsw(n, kk >> 3) + (kk & 7) * 2;
    unsigned char* base = WT_buf + (size_t)c * CHUNK_BYTES + off;
    *(__nv_bfloat16*)(base)         = hb;   // hi term
    *(__nv_bfloat16*)(base + WTERM) = lb;   // lo term
}

// ------------- main kernel -------------
__global__ void __launch_bounds__(NT, 2)
cin_hmma_kernel(const float* __restrict__ X,
                const float* __restrict__ B0, const float* __restrict__ B1,
                const float* __restrict__ B2, float* __restrict__ out)
{
    extern __shared__ __align__(16) char smem[];
    float* x0t  = (float*)(smem + SM_X0T);   // [row][36] (f stride)
    float* st   = (float*)(smem + SM_ST);    // [row][132] (g stride)
    float* bias = (float*)(smem + SM_BIAS);  // [384]
    const uint32_t wsm = smem_u32(smem) + SM_W;

    const int tid = threadIdx.x, wid = tid >> 5, lane = tid & 31;
    const int wm = wid >> 1, wn = wid & 1;     // warp grid 4(m=batch) x 2(n)
    const int b0g = blockIdx.x * 4;
    const int r0 = lane >> 2;                  // row-in-frag 0..7
    const int c0 = (lane & 3) * 2;             // col pair base
    const uint32_t t16 = (uint32_t)tid * 16;

    // precomputed stage base addresses
    const uint32_t wstage0 = wsm;
    const uint32_t wstage1 = wsm + CHUNK_BYTES;
    const uint32_t wstage2 = wsm + 2 * CHUNK_BYTES;

    // ---- issue cp.async for chunks 0 and 1 immediately ----
    {
        const unsigned char* s0 = WT_buf + t16;
        cpasync16(wstage0 + t16,        s0);
        cpasync16(wstage0 + t16 + 4096, s0 + 4096);
        CP_COMMIT();
        const unsigned char* s1 = WT_buf + CHUNK_BYTES + t16;
        cpasync16(wstage1 + t16,        s1);
        cpasync16(wstage1 + t16 + 4096, s1 + 4096);
        CP_COMMIT();
    }

    // ---- load x0 transposed + init state + bias ----
    {
        const float* Xb = X + (size_t)b0g * 1024;
        for (int i = tid; i < 4096; i += NT) {
            int b = i >> 10, f = (i >> 5) & 31, d = i & 31;
            float v = Xb[i];
            int row = b * 32 + d;
            x0t[row * 36 + f] = v;
            st[row * 132 + f] = v;     // layer-0 state = x0 (g = f)
        }
        for (int i = tid; i < 128; i += NT) {
            bias[i] = B0[i]; bias[128 + i] = B1[i]; bias[256 + i] = B2[i];
        }
    }
    CP_WAIT1();          // chunk 0 landed (chunk 1 may still be in flight)
    __syncthreads();     // x0/st/bias + chunk 0 visible

    // per-j ldsm swizzled offsets within a term
    const int kh = (lane >> 3) & 1;
    uint32_t nroff[4];
    #pragma unroll
    for (int j = 0; j < 4; ++j) {
        const int nrow = (wn * 8 + 2 * j + ((lane >> 4) & 1)) * 8 + (lane & 7);
        nroff[j] = (uint32_t)wsw(nrow, kh);
    }

    uint32_t bh[4][4], bl[4][4];    // current chunk's B fragments
    uint32_t ah[2][4], al[2][4];    // current chunk's A fragments

    // prime B for chunk 0 (stage 0)
    #pragma unroll
    for (int j = 0; j < 4; ++j)
        ldsm4(wstage0 + nroff[j], bh[j][0], bh[j][1], bh[j][2], bh[j][3]);
    #pragma unroll
    for (int j = 0; j < 4; ++j)
        ldsm4(wstage0 + WTERM + nroff[j], bl[j][0], bl[j][1], bl[j][2], bl[j][3]);

    int cg = 0;      // global chunk counter
    int scur = 0;    // stage of current chunk
    int swr = 2;     // stage cp.async writes (cg+2)
    const unsigned char* wnext = WT_buf + 2 * (size_t)CHUNK_BYTES + t16;  // src for cg+2

    #pragma unroll 1
    for (int l = 0; l < 3; ++l) {
        const int lg2 = (l == 0) ? 1 : 3;        // chunks per f = fk/16
        const int nchunk = (l == 0) ? 64 : 256;

        float acc[2][8][4];
        #pragma unroll
        for (int fr = 0; fr < 2; ++fr)
            #pragma unroll
            for (int nt = 0; nt < 8; ++nt)
                #pragma unroll
                for (int q = 0; q < 4; ++q) acc[fr][nt][q] = 0.f;

        auto build_A = [&](int cc) {
            const int f = cc >> lg2;
            const int g0 = ((cc & ((1 << lg2) - 1)) << 4) + c0;
            #pragma unroll
            for (int fr = 0; fr < 2; ++fr) {
                #pragma unroll
                for (int j2 = 0; j2 < 2; ++j2) {
                    const int row = wm * 32 + r0 + fr * 16 + j2 * 8;
                    const float x = x0t[row * 36 + f];
                    const float2 p0 = *(const float2*)(st + row * 132 + g0);
                    const float2 p1 = *(const float2*)(st + row * 132 + g0 + 8);
                    float z00 = x * p0.x, z01 = x * p0.y;
                    float z10 = x * p1.x, z11 = x * p1.y;
                    uint32_t h0 = pkbf(z00, z01), h1 = pkbf(z10, z11);
                    al[fr][j2]     = pkbf(z00 - bflo(h0), z01 - bfhi(h0));
                    al[fr][2 + j2] = pkbf(z10 - bflo(h1), z11 - bfhi(h1));
                    ah[fr][j2]     = h0;
                    ah[fr][2 + j2] = h1;
                }
            }
        };

        auto burst48 = [&]() {
            #pragma unroll
            for (int j = 0; j < 4; ++j) {
                mma16816(acc[0][2 * j],     ah[0], bh[j][0], bh[j][1]);
                mma16816(acc[1][2 * j],     ah[1], bh[j][0], bh[j][1]);
                mma16816(acc[0][2 * j + 1], ah[0], bh[j][2], bh[j][3]);
                mma16816(acc[1][2 * j + 1], ah[1], bh[j][2], bh[j][3]);
                mma16816(acc[0][2 * j],     al[0], bh[j][0], bh[j][1]);
                mma16816(acc[1][2 * j],     al[1], bh[j][0], bh[j][1]);
                mma16816(acc[0][2 * j + 1], al[0], bh[j][2], bh[j][3]);
                mma16816(acc[1][2 * j + 1], al[1], bh[j][2], bh[j][3]);
                mma16816(acc[0][2 * j],     ah[0], bl[j][0], bl[j][1]);
                mma16816(acc[1][2 * j],     ah[1], bl[j][0], bl[j][1]);
                mma16816(acc[0][2 * j + 1], ah[0], bl[j][2], bl[j][3]);
                mma16816(acc[1][2 * j + 1], ah[1], bl[j][2], bl[j][3]);
            }
        };

        // one chunk step; event order identical to R7; barrier optional
        auto step = [&](int ccL, bool dobar) {
            // cp.async for chunk cg+2 into stage swr (readers ran at iter cg-2;
            // separated by the pair barrier — reuse distance 2)
            if (cg + 2 < KCH) {
                const uint32_t dst = (swr == 0) ? wstage0 : (swr == 1) ? wstage1 : wstage2;
                cpasync16(dst + t16,        wnext);
                cpasync16(dst + t16 + 4096, wnext + 4096);
                CP_COMMIT();
            }

            // 48-MMA burst for chunk cg (A and B already in registers)
            burst48();

            // A for next chunk of this layer
            if (ccL + 1 < nchunk) build_A(ccL + 1);

            // B for chunk cg+1 (pre-barrier ldsm — R7's key invariant)
            if (cg + 1 < KCH) {
                if (cg + 2 < KCH) { CP_WAIT1(); } else { CP_WAIT0(); }
                const int snx = (scur == 2) ? 0 : scur + 1;
                const uint32_t sb2 = (snx == 0) ? wstage0 : (snx == 1) ? wstage1 : wstage2;
                #pragma unroll
                for (int j = 0; j < 4; ++j)
                    ldsm4(sb2 + nroff[j], bh[j][0], bh[j][1], bh[j][2], bh[j][3]);
                #pragma unroll
                for (int j = 0; j < 4; ++j)
                    ldsm4(sb2 + WTERM + nroff[j], bl[j][0], bl[j][1], bl[j][2], bl[j][3]);
            }

            if (dobar) __syncthreads();   // only at pair boundaries

            scur = (scur == 2) ? 0 : scur + 1;
            swr  = (swr == 2) ? 0 : swr + 1;
            ++cg;
            wnext += CHUNK_BYTES;
        };

        build_A(0);   // state is synced at this point

        #pragma unroll 1
        for (int cc = 0; cc < nchunk; cc += 2) {
            step(cc, false);      // even chunk: no barrier
            step(cc + 1, true);   // odd chunk: pair barrier
        }

        // ---- epilogue: output reduction (sum over d) + state update ----
        const int bgl = b0g + wm;
        #pragma unroll
        for (int nt = 0; nt < 8; ++nt) {
            float s0 = acc[0][nt][0] + acc[0][nt][2] + acc[1][nt][0] + acc[1][nt][2];
            float s1 = acc[0][nt][1] + acc[0][nt][3] + acc[1][nt][1] + acc[1][nt][3];
            #pragma unroll
            for (int off = 4; off <= 16; off <<= 1) {
                s0 += __shfl_xor_sync(0xffffffffu, s0, off);
                s1 += __shfl_xor_sync(0xffffffffu, s1, off);
            }
            if (lane < 4) {
                const int col = wn * 64 + nt * 8 + c0;
                float2 o;
                o.x = s0 + 32.0f * bias[l * 128 + col];
                o.y = s1 + 32.0f * bias[l * 128 + col + 1];
                *(float2*)(out + (size_t)bgl * 384 + l * 128 + col) = o;
            }
        }

        if (l < 2) {
            // state[row][h] = C[row][h] + bias_l[h]
            // (pair barrier at the layer's last chunk already fenced all
            //  build_A reads of st; this write runs post-barrier)
            #pragma unroll
            for (int fr = 0; fr < 2; ++fr) {
                #pragma unroll
                for (int nt = 0; nt < 8; ++nt) {
                    const int col = wn * 64 + nt * 8 + c0;
                    const float bx = bias[l * 128 + col];
                    const float by = bias[l * 128 + col + 1];
                    const int rowa = wm * 32 + r0 + fr * 16;
                    float2 v0, v1;
                    v0.x = acc[fr][nt][0] + bx; v0.y = acc[fr][nt][1] + by;
                    v1.x = acc[fr][nt][2] + bx; v1.y = acc[fr][nt][3] + by;
                    *(float2*)(st + rowa * 132 + col)       = v0;
                    *(float2*)(st + (rowa + 8) * 132 + col) = v1;
                }
            }
            __syncthreads();   // state visible before next layer's A builds
        }
    }
}

extern "C" void kernel_launch(void* const* d_in, const int* in_sizes, int n_in,
                              void* d_out, int out_size) {
    const float* X  = (const float*)d_in[0];
    const float* W0 = (const float*)d_in[1];
    const float* W1 = (const float*)d_in[2];
    const float* W2 = (const float*)d_in[3];
    const float* B0 = (const float*)d_in[4];
    const float* B1 = (const float*)d_in[5];
    const float* B2 = (const float*)d_in[6];
    float* out = (float*)d_out;

    const int B = in_sizes[0] / 1024;

    cudaFuncSetAttribute(cin_hmma_kernel,
                         cudaFuncAttributeMaxDynamicSharedMemorySize, SMEM_TOTAL);

    prep_w<<<(9216 * 128 + 255) / 256, 256>>>(W0, W1, W2);
    cin_hmma_kernel<<<B / 4, NT, SMEM_TOTAL>>>(X, B0, B1, B2, out);
}

// round 14
// speedup vs baseline: 1.1333x; 1.0967x over previous
#include <cuda_runtime.h>
#include <cuda_bf16.h>
#include <cstdint>

// CIN (xDeepFM) fused 3-layer kernel via mma.sync (HMMA) bf16 3-term split.
// Round 13: exact R7 structure (best measured: 590us) + non-structural
// micro-cuts in the per-chunk instruction stream: hoisted row base pointers,
// x-loads once per f, incremental global W pointer. Event order, barrier
// cadence, and all math are bit-identical to R7.

#define NT 256
#define KCH 576                 // total 16-wide k chunks: 64 + 256 + 256
#define WTERM 4096              // 128 n-rows * 32B (16 bf16), swizzled
#define CHUNK_BYTES (2 * WTERM) // 8192: hi term + lo term
#define NSTAGE 3

// smem byte offsets
#define SM_X0T   0                  // 128 rows * 36 f32 = 18432
#define SM_ST    18432              // 128 rows * 132 f32 = 67584
#define SM_W     86016              // 3 stages * 8192 = 24576
#define SM_BIAS  110592             // 384 f32 = 1536
#define SMEM_TOTAL 112128

__device__ __align__(16) unsigned char WT_buf[(size_t)KCH * CHUNK_BYTES]; // 4.7MB

// ------------- helpers -------------
__device__ __forceinline__ uint32_t smem_u32(const void* p) {
    uint32_t a;
    asm("{ .reg .u64 t; cvta.to.shared.u64 t, %1; cvt.u32.u64 %0, t; }" : "=r"(a) : "l"(p));
    return a;
}
__device__ __forceinline__ uint32_t pkbf(float lo, float hi) {
    uint32_t r;  // first asm operand -> high half
    asm("cvt.rn.bf16x2.f32 %0, %1, %2;" : "=r"(r) : "f"(hi), "f"(lo));
    return r;
}
__device__ __forceinline__ float bflo(uint32_t p) { return __uint_as_float(p << 16); }
__device__ __forceinline__ float bfhi(uint32_t p) { return __uint_as_float(p & 0xffff0000u); }

__device__ __forceinline__ void ldsm4(uint32_t a, uint32_t& r0, uint32_t& r1,
                                      uint32_t& r2, uint32_t& r3) {
    asm volatile("ldmatrix.sync.aligned.m8n8.x4.shared.b16 {%0,%1,%2,%3}, [%4];"
                 : "=r"(r0), "=r"(r1), "=r"(r2), "=r"(r3) : "r"(a));
}
__device__ __forceinline__ void mma16816(float* c, const uint32_t* a, uint32_t b0, uint32_t b1) {
    asm volatile("mma.sync.aligned.m16n8k16.row.col.f32.bf16.bf16.f32 "
                 "{%0,%1,%2,%3}, {%4,%5,%6,%7}, {%8,%9}, {%0,%1,%2,%3};"
                 : "+f"(c[0]), "+f"(c[1]), "+f"(c[2]), "+f"(c[3])
                 : "r"(a[0]), "r"(a[1]), "r"(a[2]), "r"(a[3]), "r"(b0), "r"(b1));
}
__device__ __forceinline__ void cpasync16(uint32_t dst, const void* src) {
    asm volatile("cp.async.cg.shared.global [%0], [%1], 16;" :: "r"(dst), "l"(src) : "memory");
}
#define CP_COMMIT() asm volatile("cp.async.commit_group;" ::: "memory")
#define CP_WAIT0()  asm volatile("cp.async.wait_group 0;" ::: "memory")
#define CP_WAIT1()  asm volatile("cp.async.wait_group 1;" ::: "memory")

// swizzled byte offset of the 16B half (n-row, khalf) within one term
__device__ __host__ __forceinline__ int wsw(int n, int khalf) {
    return n * 32 + ((khalf ^ ((n >> 2) & 1)) << 4);
}

// ------------- prep: split W -> bf16 hi/lo, swizzled chunk layout == smem -------------
__global__ void prep_w(const float* __restrict__ W0, const float* __restrict__ W1,
                       const float* __restrict__ W2) {
    int i = blockIdx.x * blockDim.x + threadIdx.x;   // over 9216*128
    if (i >= 9216 * 128) return;
    int k = i >> 7, n = i & 127;
    float w;
    if (k < 1024)      w = W0[k * 128 + n];
    else if (k < 5120) w = W1[(k - 1024) * 128 + n];
    else               w = W2[(k - 5120) * 128 + n];
    __nv_bfloat16 hb = __float2bfloat16(w);
    __nv_bfloat16 lb = __float2bfloat16(w - __bfloat162float(hb));
    int c = k >> 4, kk = k & 15;
    int off = wsw(n, kk >> 3) + (kk & 7) * 2;
    unsigned char* base = WT_buf + (size_t)c * CHUNK_BYTES + off;
    *(__nv_bfloat16*)(base)         = hb;   // hi term
    *(__nv_bfloat16*)(base + WTERM) = lb;   // lo term
}

// ------------- main kernel -------------
__global__ void __launch_bounds__(NT, 2)
cin_hmma_kernel(const float* __restrict__ X,
                const float* __restrict__ B0, const float* __restrict__ B1,
                const float* __restrict__ B2, float* __restrict__ out)
{
    extern __shared__ __align__(16) char smem[];
    float* x0t  = (float*)(smem + SM_X0T);   // [row][36] (f stride)
    float* st   = (float*)(smem + SM_ST);    // [row][132] (g stride)
    float* bias = (float*)(smem + SM_BIAS);  // [384]
    const uint32_t wsm = smem_u32(smem) + SM_W;

    const int tid = threadIdx.x, wid = tid >> 5, lane = tid & 31;
    const int wm = wid >> 1, wn = wid & 1;     // warp grid 4(m=batch) x 2(n)
    const int b0g = blockIdx.x * 4;
    const int r0 = lane >> 2;                  // row-in-frag 0..7
    const int c0 = (lane & 3) * 2;             // col pair base
    const uint32_t t16 = (uint32_t)tid * 16;

    const uint32_t wstage0 = wsm;
    const uint32_t wstage1 = wsm + CHUNK_BYTES;
    const uint32_t wstage2 = wsm + 2 * CHUNK_BYTES;

    // ---- issue cp.async for chunks 0 and 1 immediately ----
    {
        const unsigned char* s0 = WT_buf + t16;
        cpasync16(wstage0 + t16,        s0);
        cpasync16(wstage0 + t16 + 4096, s0 + 4096);
        CP_COMMIT();
        const unsigned char* s1 = WT_buf + CHUNK_BYTES + t16;
        cpasync16(wstage1 + t16,        s1);
        cpasync16(wstage1 + t16 + 4096, s1 + 4096);
        CP_COMMIT();
    }

    // ---- load x0 transposed + init state + bias ----
    {
        const float* Xb = X + (size_t)b0g * 1024;
        for (int i = tid; i < 4096; i += NT) {
            int b = i >> 10, f = (i >> 5) & 31, d = i & 31;
            float v = Xb[i];
            int row = b * 32 + d;
            x0t[row * 36 + f] = v;
            st[row * 132 + f] = v;     // layer-0 state = x0 (g = f)
        }
        for (int i = tid; i < 128; i += NT) {
            bias[i] = B0[i]; bias[128 + i] = B1[i]; bias[256 + i] = B2[i];
        }
    }
    CP_WAIT1();          // chunk 0 landed (chunk 1 may still be in flight)
    __syncthreads();     // x0/st/bias + chunk 0 visible

    // per-j ldsm swizzled offsets within a term
    const int kh = (lane >> 3) & 1;
    uint32_t nroff[4];
    #pragma unroll
    for (int j = 0; j < 4; ++j) {
        const int nrow = (wn * 8 + 2 * j + ((lane >> 4) & 1)) * 8 + (lane & 7);
        nroff[j] = (uint32_t)wsw(nrow, kh);
    }

    // ---- hoisted loop-invariant per-thread row base pointers ----
    // idx = fr*2 + j2, row = wm*32 + r0 + fr*16 + j2*8
    const float* st_rowp[4];
    const float* x0_rowp[4];
    #pragma unroll
    for (int fr = 0; fr < 2; ++fr)
        #pragma unroll
        for (int j2 = 0; j2 < 2; ++j2) {
            const int row = wm * 32 + r0 + fr * 16 + j2 * 8;
            st_rowp[fr * 2 + j2] = st + row * 132 + c0;
            x0_rowp[fr * 2 + j2] = x0t + row * 36;
        }

    uint32_t bh[4][4], bl[4][4];    // current chunk's B fragments
    uint32_t ah[2][4], al[2][4];    // current chunk's A fragments
    float xv[4];                    // hoisted x values (reloaded per f)

    // prime B for chunk 0 (stage 0)
    #pragma unroll
    for (int j = 0; j < 4; ++j)
        ldsm4(wstage0 + nroff[j], bh[j][0], bh[j][1], bh[j][2], bh[j][3]);
    #pragma unroll
    for (int j = 0; j < 4; ++j)
        ldsm4(wstage0 + WTERM + nroff[j], bl[j][0], bl[j][1], bl[j][2], bl[j][3]);

    int cg = 0;      // global chunk counter
    int scur = 0;    // stage of current chunk
    int swr = 2;     // stage cp.async writes (cg+2)
    const unsigned char* wnext = WT_buf + 2 * (size_t)CHUNK_BYTES + t16;  // src for cg+2

    #pragma unroll 1
    for (int l = 0; l < 3; ++l) {
        const int lg2 = (l == 0) ? 1 : 3;        // chunks per f = fk/16
        const int fmask = (1 << lg2) - 1;
        const int nchunk = (l == 0) ? 64 : 256;

        float acc[2][8][4];
        #pragma unroll
        for (int fr = 0; fr < 2; ++fr)
            #pragma unroll
            for (int nt = 0; nt < 8; ++nt)
                #pragma unroll
                for (int q = 0; q < 4; ++q) acc[fr][nt][q] = 0.f;

        auto build_A = [&](int cc) {
            if ((cc & fmask) == 0) {            // new f: reload x values
                const int f = cc >> lg2;
                #pragma unroll
                for (int i = 0; i < 4; ++i) xv[i] = x0_rowp[i][f];
            }
            const int g0 = (cc & fmask) << 4;
            #pragma unroll
            for (int fr = 0; fr < 2; ++fr) {
                #pragma unroll
                for (int j2 = 0; j2 < 2; ++j2) {
                    const int idx = fr * 2 + j2;
                    const float x = xv[idx];
                    const float2 p0 = *(const float2*)(st_rowp[idx] + g0);
                    const float2 p1 = *(const float2*)(st_rowp[idx] + g0 + 8);
                    float z00 = x * p0.x, z01 = x * p0.y;
                    float z10 = x * p1.x, z11 = x * p1.y;
                    uint32_t h0 = pkbf(z00, z01), h1 = pkbf(z10, z11);
                    al[fr][j2]     = pkbf(z00 - bflo(h0), z01 - bfhi(h0));
                    al[fr][2 + j2] = pkbf(z10 - bflo(h1), z11 - bfhi(h1));
                    ah[fr][j2]     = h0;
                    ah[fr][2 + j2] = h1;
                }
            }
        };

        build_A(0);   // state is synced at this point

        #pragma unroll 1
        for (int cc = 0; cc < nchunk; ++cc) {
            // ---- issue cp.async for chunk cg+2 into stage swr ----
            if (cg + 2 < KCH) {
                const uint32_t dst = (swr == 0) ? wstage0 : (swr == 1) ? wstage1 : wstage2;
                cpasync16(dst + t16,        wnext);
                cpasync16(dst + t16 + 4096, wnext + 4096);
                CP_COMMIT();
            }

            // ---- 48-MMA burst for chunk cg (A and B already in registers) ----
            #pragma unroll
            for (int j = 0; j < 4; ++j) {
                mma16816(acc[0][2 * j],     ah[0], bh[j][0], bh[j][1]);
                mma16816(acc[1][2 * j],     ah[1], bh[j][0], bh[j][1]);
                mma16816(acc[0][2 * j + 1], ah[0], bh[j][2], bh[j][3]);
                mma16816(acc[1][2 * j + 1], ah[1], bh[j][2], bh[j][3]);
                mma16816(acc[0][2 * j],     al[0], bh[j][0], bh[j][1]);
                mma16816(acc[1][2 * j],     al[1], bh[j][0], bh[j][1]);
                mma16816(acc[0][2 * j + 1], al[0], bh[j][2], bh[j][3]);
                mma16816(acc[1][2 * j + 1], al[1], bh[j][2], bh[j][3]);
                mma16816(acc[0][2 * j],     ah[0], bl[j][0], bl[j][1]);
                mma16816(acc[1][2 * j],     ah[1], bl[j][0], bl[j][1]);
                mma16816(acc[0][2 * j + 1], ah[0], bl[j][2], bl[j][3]);
                mma16816(acc[1][2 * j + 1], ah[1], bl[j][2], bl[j][3]);
            }

            // ---- A for next chunk of this layer ----
            if (cc + 1 < nchunk) build_A(cc + 1);

            // ---- B for chunk cg+1 (pre-barrier ldsm — R7's key invariant) ----
            if (cg + 1 < KCH) {
                if (cg + 2 < KCH) { CP_WAIT1(); } else { CP_WAIT0(); }
                const int snx = (scur == 2) ? 0 : scur + 1;
                const uint32_t sb2 = (snx == 0) ? wstage0 : (snx == 1) ? wstage1 : wstage2;
                #pragma unroll
                for (int j = 0; j < 4; ++j)
                    ldsm4(sb2 + nroff[j], bh[j][0], bh[j][1], bh[j][2], bh[j][3]);
                #pragma unroll
                for (int j = 0; j < 4; ++j)
                    ldsm4(sb2 + WTERM + nroff[j], bl[j][0], bl[j][1], bl[j][2], bl[j][3]);
            }

            // ---- WAR fence: all warps done reading stage scur (R7 cadence) ----
            __syncthreads();

            scur = (scur == 2) ? 0 : scur + 1;
            swr  = (swr == 2) ? 0 : swr + 1;
            ++cg;
            wnext += CHUNK_BYTES;
        }

        // ---- epilogue: output reduction (sum over d) + state update ----
        const int bgl = b0g + wm;
        #pragma unroll
        for (int nt = 0; nt < 8; ++nt) {
            float s0 = acc[0][nt][0] + acc[0][nt][2] + acc[1][nt][0] + acc[1][nt][2];
            float s1 = acc[0][nt][1] + acc[0][nt][3] + acc[1][nt][1] + acc[1][nt][3];
            #pragma unroll
            for (int off = 4; off <= 16; off <<= 1) {
                s0 += __shfl_xor_sync(0xffffffffu, s0, off);
                s1 += __shfl_xor_sync(0xffffffffu, s1, off);
            }
            if (lane < 4) {
                const int col = wn * 64 + nt * 8 + c0;
                float2 o;
                o.x = s0 + 32.0f * bias[l * 128 + col];
                o.y = s1 + 32.0f * bias[l * 128 + col + 1];
                *(float2*)(out + (size_t)bgl * 384 + l * 128 + col) = o;
            }
        }

        if (l < 2) {
            // state[row][h] = C[row][h] + bias_l[h]
            #pragma unroll
            for (int fr = 0; fr < 2; ++fr) {
                #pragma unroll
                for (int nt = 0; nt < 8; ++nt) {
                    const int col = wn * 64 + nt * 8 + c0;
                    const float bx = bias[l * 128 + col];
                    const float by = bias[l * 128 + col + 1];
                    const int rowa = wm * 32 + r0 + fr * 16;
                    float2 v0, v1;
                    v0.x = acc[fr][nt][0] + bx; v0.y = acc[fr][nt][1] + by;
                    v1.x = acc[fr][nt][2] + bx; v1.y = acc[fr][nt][3] + by;
                    *(float2*)(st + rowa * 132 + col)       = v0;
                    *(float2*)(st + (rowa + 8) * 132 + col) = v1;
                }
            }
            __syncthreads();   // state visible before next layer's A builds
        }
    }
}

extern "C" void kernel_launch(void* const* d_in, const int* in_sizes, int n_in,
                              void* d_out, int out_size) {
    const float* X  = (const float*)d_in[0];
    const float* W0 = (const float*)d_in[1];
    const float* W1 = (const float*)d_in[2];
    const float* W2 = (const float*)d_in[3];
    const float* B0 = (const float*)d_in[4];
    const float* B1 = (const float*)d_in[5];
    const float* B2 = (const float*)d_in[6];
    float* out = (float*)d_out;

    const int B = in_sizes[0] / 1024;

    cudaFuncSetAttribute(cin_hmma_kernel,
                         cudaFuncAttributeMaxDynamicSharedMemorySize, SMEM_TOTAL);

    prep_w<<<(9216 * 128 + 255) / 256, 256>>>(W0, W1, W2);
    cin_hmma_kernel<<<B / 4, NT, SMEM_TOTAL>>>(X, B0, B1, B2, out);
}